// round 5
// baseline (speedup 1.0000x reference)
#include <cuda_runtime.h>
#include <cuda_bf16.h>
#include <math.h>

// RNNTAlignDistillLoss — B=8, T=256, U=64, V=1024.
// Inputs: d_in[0]=logits f32[B,T,U,V], d_in[1]=ys (unused),
//         d_in[2]=soft_labels f32[B,U,V], d_in[3]=aligns i32[B,U],
//         d_in[4]=xlens (unused), d_in[5]=ylens i32[B].
// Output: scalar f32 loss.
//
// loss_b = (Σ s·x − log(Σ e^x)) / ylen  (Σs = 1 over full V),
// loss = −Σ_b loss_b / B.
//
// 8 CTAs × 32 threads: one SM per batch element — removes the single-SM
// LSU/MUFU serialization of the 1-CTA version. Deterministic combine:
// per-CTA partial slots + atomic counter electing the last CTA, which
// sums partials in fixed order, writes out, and resets the counter to
// its initial (zero) state for the next graph replay.

#define B_ 8
#define T_ 256
#define U_ 64
#define V_ 1024
#define LN2 0.6931471805599453f

__device__ float g_part[B_];
__device__ int   g_cnt;        // zero-initialized; restored to 0 every call

__global__ __launch_bounds__(32, 1)
void rnnt_align_distill_loss_kernel(const float* __restrict__ logits,
                                    const float* __restrict__ soft_labels,
                                    const int*   __restrict__ aligns,
                                    const int*   __restrict__ ylens,
                                    float*       __restrict__ out)
{
    const int b    = blockIdx.x;        // batch element (0..7)
    const int lane = threadIdx.x;       // 0..31

    // --- depth-1 index loads (independent, overlap) -------------------------
    const int  ylen = ylens[b];
    const int2 arow = ((const int2*)(aligns + b * U_))[lane];  // full aligns row

    const int u  = ylen - 1;
    const int sx = __shfl_sync(0xFFFFFFFFu, arow.x, u >> 1);
    const int sy = __shfl_sync(0xFFFFFFFFu, arow.y, u >> 1);
    const int t  = (u & 1) ? sy : sx;

    const float4* __restrict__ sel = (const float4*)(logits +
                        (((size_t)b * T_ + t) * U_ + u) * V_);
    const float4* __restrict__ sl  = (const float4*)(soft_labels +
                        ((size_t)b * U_ + u) * V_);

    // --- fused interleaved pass over 1024 elems (32 floats/thread) ----------
    float se  = 0.0f;   // Σ e^x
    float dot = 0.0f;   // Σ s·x
    #pragma unroll
    for (int k = 0; k < 8; k++) {
        const float4 x = sel[lane + k * 32];
        const float4 s = sl [lane + k * 32];
        se  += __expf(x.x) + __expf(x.y) + __expf(x.z) + __expf(x.w);
        dot += s.x * x.x + s.y * x.y + s.z * x.z + s.w * x.w;
    }

    // --- warp reduction (two independent chains) ----------------------------
    #pragma unroll
    for (int off = 16; off > 0; off >>= 1) {
        se  += __shfl_xor_sync(0xFFFFFFFFu, se,  off);
        dot += __shfl_xor_sync(0xFFFFFFFFu, dot, off);
    }

    // --- publish partial, elect last CTA -------------------------------------
    int last = 0;
    if (lane == 0) {
        g_part[b] = (dot - __log2f(se) * LN2) / (float)ylen;
        __threadfence();
        last = (atomicAdd(&g_cnt, 1) == B_ - 1);
    }
    last = __shfl_sync(0xFFFFFFFFu, last, 0);

    if (last) {
        __threadfence();   // acquire: see all partial writes
        float v = (lane < B_) ? g_part[lane] : 0.0f;
        #pragma unroll
        for (int off = 4; off > 0; off >>= 1)
            v += __shfl_xor_sync(0xFFFFFFFFu, v, off);
        if (lane == 0) {
            out[0] = -v * (1.0f / (float)B_);
            g_cnt = 0;                 // restore init state for next replay
        }
    }
}

extern "C" void kernel_launch(void* const* d_in, const int* in_sizes, int n_in,
                              void* d_out, int out_size)
{
    const float* logits      = (const float*)d_in[0];
    const float* soft_labels = (const float*)d_in[2];
    const int*   aligns      = (const int*)d_in[3];
    const int*   ylens       = (const int*)d_in[5];
    float*       out         = (float*)d_out;

    rnnt_align_distill_loss_kernel<<<B_, 32>>>(logits, soft_labels, aligns, ylens, out);
}

// round 6
// speedup vs baseline: 1.0048x; 1.0048x over previous
#include <cuda_runtime.h>
#include <cuda_bf16.h>
#include <math.h>

// RNNTAlignDistillLoss — B=8, T=256, U=64, V=1024.
// Inputs: d_in[0]=logits f32[B,T,U,V], d_in[1]=ys (unused),
//         d_in[2]=soft_labels f32[B,U,V], d_in[3]=aligns i32[B,U],
//         d_in[4]=xlens (unused), d_in[5]=ylens i32[B].
// Output: scalar f32 loss.
//
// loss_b = (Σ s·x − log(Σ e^x)) / ylen  (Σs = 1 over full V),
// loss = −Σ_b loss_b / B.
//
// One CTA, 512 threads = 16 warps; warps (2b, 2b+1) handle batch b with
// 16 floats/thread. Per-warp partial (se, dot) pairs combined in smem,
// final log/divide/sum done by warp 0 entirely in shuffles.

#define B_ 8
#define T_ 256
#define U_ 64
#define V_ 1024
#define LN2 0.6931471805599453f

__global__ __launch_bounds__(512, 1)
void rnnt_align_distill_loss_kernel(const float* __restrict__ logits,
                                    const float* __restrict__ soft_labels,
                                    const int*   __restrict__ aligns,
                                    const int*   __restrict__ ylens,
                                    float*       __restrict__ out)
{
    const int w    = threadIdx.x >> 5;     // warp 0..15
    const int b    = w >> 1;               // batch element 0..7
    const int sub  = w & 1;                // half selector within batch
    const int lane = threadIdx.x & 31;

    __shared__ float2 sm_red[16];          // per-warp (se, dot)
    __shared__ float  sm_inv_ylen[B_];     // 1/ylen per batch

    // --- depth-1 index loads (independent, overlap) -------------------------
    const int  ylen = ylens[b];
    const int2 arow = ((const int2*)(aligns + b * U_))[lane];  // full row

    const int u  = ylen - 1;
    const int sx = __shfl_sync(0xFFFFFFFFu, arow.x, u >> 1);
    const int sy = __shfl_sync(0xFFFFFFFFu, arow.y, u >> 1);
    const int t  = (u & 1) ? sy : sx;

    const float4* __restrict__ sel = (const float4*)(logits +
                        (((size_t)b * T_ + t) * U_ + u) * V_);
    const float4* __restrict__ sl  = (const float4*)(soft_labels +
                        ((size_t)b * U_ + u) * V_);

    // --- fused pass: 4 float4 chunks per thread (16 floats) ------------------
    float se  = 0.0f;
    float dot = 0.0f;
    #pragma unroll
    for (int k = 0; k < 4; k++) {
        const int idx = lane + sub * 32 + k * 64;   // covers 0..255 float4s
        const float4 x = sel[idx];
        const float4 s = sl [idx];
        se  += __expf(x.x) + __expf(x.y) + __expf(x.z) + __expf(x.w);
        dot += s.x * x.x + s.y * x.y + s.z * x.z + s.w * x.w;
    }

    // --- warp reduction (two independent chains) ----------------------------
    #pragma unroll
    for (int off = 16; off > 0; off >>= 1) {
        se  += __shfl_xor_sync(0xFFFFFFFFu, se,  off);
        dot += __shfl_xor_sync(0xFFFFFFFFu, dot, off);
    }

    if (lane == 0) {
        sm_red[w] = make_float2(se, dot);
        if (sub == 0) sm_inv_ylen[b] = 1.0f / (float)ylen;
    }
    __syncthreads();

    // --- final combine in warp 0 ---------------------------------------------
    if (threadIdx.x < 32) {
        float fse = 0.0f, fdot = 0.0f, inv = 0.0f;
        if (lane < 16) {
            const float2 p = sm_red[lane];
            fse  = p.x;
            fdot = p.y;
            inv  = sm_inv_ylen[lane >> 1];
        }
        // merge warp pairs (lanes 2b, 2b+1)
        fse  += __shfl_xor_sync(0xFFFFFFFFu, fse,  1);
        fdot += __shfl_xor_sync(0xFFFFFFFFu, fdot, 1);

        float loss = 0.0f;
        if (lane < 16 && (lane & 1) == 0)
            loss = (fdot - __log2f(fse) * LN2) * inv;

        #pragma unroll
        for (int off = 2; off <= 8; off <<= 1)
            loss += __shfl_xor_sync(0xFFFFFFFFu, loss, off);

        if (lane == 0) out[0] = -loss * (1.0f / (float)B_);
    }
}

extern "C" void kernel_launch(void* const* d_in, const int* in_sizes, int n_in,
                              void* d_out, int out_size)
{
    const float* logits      = (const float*)d_in[0];
    const float* soft_labels = (const float*)d_in[2];
    const int*   aligns      = (const int*)d_in[3];
    const int*   ylens       = (const int*)d_in[5];
    float*       out         = (float*)d_out;

    rnnt_align_distill_loss_kernel<<<1, 512>>>(logits, soft_labels, aligns, ylens, out);
}